// round 3
// baseline (speedup 1.0000x reference)
#include <cuda_runtime.h>
#include <cstdint>

#define FULLMASK 0xffffffffu

static constexpr int Hh      = 5;
static constexpr int Tt      = 512;
static constexpr int Bb      = 8192;
static constexpr int CHUNK   = 16;          // timesteps per smem chunk
static constexpr int NCHUNK  = Tt / CHUNK;  // 32
static constexpr int EPB     = 30;          // elements per block
static constexpr int BLOCK1  = 160;         // 5 warps * 32
static constexpr int GRID1   = (Bb + EPB - 1) / EPB;  // 274
static constexpr int ROWF    = Tt * Hh;     // 2560 floats per batch row
static constexpr int CH_FL   = CHUNK * Hh;  // 80 floats per element per chunk
static constexpr int STAGE_N = EPB * CH_FL; // 2400 floats per chunk per block
static constexpr int PF      = STAGE_N / BLOCK1; // 15 prefetch regs per thread

__device__ float g_hlast[Bb * Hh];

// ---------- packed f32x2 helpers ----------
__device__ __forceinline__ unsigned long long pack2(float lo, float hi) {
    unsigned long long r;
    asm("mov.b64 %0, {%1, %2};" : "=l"(r) : "f"(lo), "f"(hi));
    return r;
}
__device__ __forceinline__ void unpack2(unsigned long long v, float& lo, float& hi) {
    asm("mov.b64 {%0, %1}, %2;" : "=f"(lo), "=f"(hi) : "l"(v));
}
__device__ __forceinline__ unsigned long long fma2(unsigned long long a,
                                                   unsigned long long b,
                                                   unsigned long long c) {
    unsigned long long d;
    asm("fma.rn.f32x2 %0, %1, %2, %3;" : "=l"(d) : "l"(a), "l"(b), "l"(c));
    return d;
}
__device__ __forceinline__ float tanh_fast(float x) {
    float y;
    asm("tanh.approx.f32 %0, %1;" : "=f"(y) : "f"(x));
    return y;
}

// ============================================================================
// Kernel 1: LSTM recurrence. 5 threads per element, 6 elements per warp.
// Thread `sub` (0..4) owns gate rows {sub, sub+5, sub+10, sub+15} = {i,f,g,o}
// and state components c[sub], h[sub]. h broadcast via shfl each step.
// Sigmoid via tanh identity with all 0.5 scale factors folded into weights:
//   acc_i = 0.5*z_i  -> i = 0.5*tanh(acc_i)+0.5   (W,b pre-scaled by 0.5)
//   internal h state hs = 2*h  (W_hh columns pre-scaled by extra 0.5)
// ============================================================================
__global__ void __launch_bounds__(BLOCK1)
lstm_kernel(const float* __restrict__ x,
            const float* __restrict__ W_ih, const float* __restrict__ W_hh,
            const float* __restrict__ b_ih, const float* __restrict__ b_hh)
{
    // x staged duplicated: [t][elem][k] stored as (v,v) pairs -> LDS.64 feeds f32x2
    __shared__ float sx[2][CHUNK * EPB * 2 * Hh];   // 2*4800 floats = 38400 B

    const int tid  = threadIdx.x;
    const int warp = tid >> 5;
    const int lane = tid & 31;

    int ew  = lane / 5;          // element slot within warp (0..5)
    int sub = lane % 5;
    const bool lane_ok = (lane < 30);
    if (!lane_ok) { ew = 5; sub = 0; }           // lanes 30/31 mirror slot 5
    const int gbase = lane_ok ? (ew * 5) : 25;   // shuffle source base

    const int elem  = warp * 6 + ew;             // 0..29 within block
    const int blk30 = blockIdx.x * EPB;
    const int gb    = blk30 + elem;
    const bool valid = lane_ok && (gb < Bb);

    // ---- load + pre-scale + pack weights ----
    unsigned long long wIF[10], wGO[10];  // [0..4] x-part, [5..9] h-part
#pragma unroll
    for (int k = 0; k < 5; ++k) {
        wIF[k]     = pack2(0.50f * W_ih[(sub     ) * 5 + k],
                           0.50f * W_ih[(sub + 5 ) * 5 + k]);
        wGO[k]     = pack2(        W_ih[(sub + 10) * 5 + k],
                           0.50f * W_ih[(sub + 15) * 5 + k]);
        wIF[5 + k] = pack2(0.25f * W_hh[(sub     ) * 5 + k],
                           0.25f * W_hh[(sub + 5 ) * 5 + k]);
        wGO[5 + k] = pack2(0.50f * W_hh[(sub + 10) * 5 + k],
                           0.25f * W_hh[(sub + 15) * 5 + k]);
    }
    const unsigned long long bIF =
        pack2(0.5f * (b_ih[sub] + b_hh[sub]),
              0.5f * (b_ih[sub + 5] + b_hh[sub + 5]));
    const unsigned long long bGO =
        pack2(       (b_ih[sub + 10] + b_hh[sub + 10]),
              0.5f * (b_ih[sub + 15] + b_hh[sub + 15]));

    // ---- stage chunk 0 ----
    for (int i = tid; i < STAGE_N; i += BLOCK1) {
        const int e = i / CH_FL, r = i - e * CH_FL;
        const int src_b = blk30 + e;
        const float v = (src_b < Bb) ? x[src_b * ROWF + r] : 0.0f;
        const int t = r / 5, k = r - t * 5;
        float* d = &sx[0][(t * EPB + e) * 10 + 2 * k];
        d[0] = v; d[1] = v;
    }
    __syncthreads();

    float c  = 0.0f;
    float hs = 0.0f;   // 2*h

    for (int ch = 0; ch < NCHUNK; ++ch) {
        // prefetch next chunk into registers (LDG latency hidden by compute)
        float pf[PF];
        if (ch + 1 < NCHUNK) {
#pragma unroll
            for (int it = 0; it < PF; ++it) {
                const int i = tid + it * BLOCK1;
                const int e = i / CH_FL, r = i - e * CH_FL;
                const int src_b = blk30 + e;
                pf[it] = (src_b < Bb) ? x[src_b * ROWF + (ch + 1) * CH_FL + r] : 0.0f;
            }
        }

        const unsigned long long* xb =
            reinterpret_cast<const unsigned long long*>(&sx[ch & 1][0]);

#pragma unroll
        for (int tl = 0; tl < CHUNK; ++tl) {
            const unsigned long long* xr = xb + (tl * EPB + elem) * 5;
            unsigned long long aIF = bIF, aGO = bGO;
#pragma unroll
            for (int k = 0; k < 5; ++k) {
                const unsigned long long xk = xr[k];   // (x_k, x_k) LDS.64
                aIF = fma2(wIF[k], xk, aIF);
                aGO = fma2(wGO[k], xk, aGO);
            }
#pragma unroll
            for (int k = 0; k < 5; ++k) {
                const float hk = __shfl_sync(FULLMASK, hs, gbase + k);
                const unsigned long long hh = pack2(hk, hk);
                aIF = fma2(wIF[5 + k], hh, aIF);
                aGO = fma2(wGO[5 + k], hh, aGO);
            }
            float zi, zf, zg, zo;
            unpack2(aIF, zi, zf);
            unpack2(aGO, zg, zo);
            const float Ti = tanh_fast(zi);
            const float Tf = tanh_fast(zf);
            const float Tg = tanh_fast(zg);
            const float To = tanh_fast(zo);
            const float u = fmaf(Tf, c, c);        // 2*f*c
            const float v = fmaf(Ti, Tg, Tg);      // 2*i*g
            c = 0.5f * (u + v);
            const float Tc = tanh_fast(c);
            hs = fmaf(To, Tc, Tc);                 // 2*o*tanh(c)
        }

        // store next chunk (other buffer; prior readers of it finished a barrier ago)
        if (ch + 1 < NCHUNK) {
#pragma unroll
            for (int it = 0; it < PF; ++it) {
                const int i = tid + it * BLOCK1;
                const int e = i / CH_FL, r = i - e * CH_FL;
                const int t = r / 5, k = r - t * 5;
                float* d = &sx[(ch + 1) & 1][(t * EPB + e) * 10 + 2 * k];
                d[0] = pf[it]; d[1] = pf[it];
            }
        }
        __syncthreads();
    }

    if (valid) g_hlast[gb * Hh + sub] = 0.5f * hs;
}

// ============================================================================
// Kernel 2: residual + MLP head. One warp per element; 32-wide shuffle GEMV.
// ============================================================================
__global__ void __launch_bounds__(256)
head_kernel(const float* __restrict__ x,
            const float* __restrict__ W1, const float* __restrict__ b1,
            const float* __restrict__ W2, const float* __restrict__ b2,
            const float* __restrict__ W3, const float* __restrict__ b3,
            float* __restrict__ out)
{
    __shared__ float sW1[32 * 5];
    __shared__ float sb1[32], sb2[32], sb3[5];
    __shared__ float sW2[32 * 33];   // padded rows: kill 32-way bank conflict
    __shared__ float sW3[5 * 33];

    const int tid = threadIdx.x;
    for (int i = tid; i < 160; i += 256) sW1[i] = W1[i];
    for (int i = tid; i < 1024; i += 256) sW2[(i >> 5) * 33 + (i & 31)] = W2[i];
    for (int i = tid; i < 160; i += 256) sW3[(i >> 5) * 33 + (i & 31)] = W3[i];
    if (tid < 32) { sb1[tid] = b1[tid]; sb2[tid] = b2[tid]; }
    if (tid < 5)  sb3[tid] = b3[tid];
    __syncthreads();

    const int warp = tid >> 5, lane = tid & 31;
    const int e = blockIdx.x * 8 + warp;   // grid sized so e < Bb always

    float res = 0.0f;
    if (lane < 5) res = g_hlast[e * Hh + lane] + x[e * ROWF + (Tt - 1) * Hh + lane];

    float a1 = sb1[lane];
#pragma unroll
    for (int k = 0; k < 5; ++k)
        a1 = fmaf(sW1[lane * 5 + k], __shfl_sync(FULLMASK, res, k), a1);
    a1 = fmaxf(a1, 0.0f);

    float a2 = sb2[lane];
#pragma unroll
    for (int k = 0; k < 32; ++k)
        a2 = fmaf(sW2[lane * 33 + k], __shfl_sync(FULLMASK, a1, k), a2);
    a2 = fmaxf(a2, 0.0f);

    const int wrow = (lane < 5) ? lane : 0;
    float o = (lane < 5) ? sb3[lane] : 0.0f;
#pragma unroll
    for (int k = 0; k < 32; ++k) {
        const float v = __shfl_sync(FULLMASK, a2, k);
        o = fmaf(sW3[wrow * 33 + k], v, o);
    }
    if (lane < 5) out[e * Hh + lane] = o;
}

// ============================================================================
extern "C" void kernel_launch(void* const* d_in, const int* in_sizes, int n_in,
                              void* d_out, int out_size) {
    const float* x    = (const float*)d_in[0];
    const float* W_ih = (const float*)d_in[1];
    const float* W_hh = (const float*)d_in[2];
    const float* b_ih = (const float*)d_in[3];
    const float* b_hh = (const float*)d_in[4];
    const float* W1   = (const float*)d_in[5];
    const float* b1   = (const float*)d_in[6];
    const float* W2   = (const float*)d_in[7];
    const float* b2   = (const float*)d_in[8];
    const float* W3   = (const float*)d_in[9];
    const float* b3   = (const float*)d_in[10];
    float* out = (float*)d_out;

    lstm_kernel<<<GRID1, BLOCK1>>>(x, W_ih, W_hh, b_ih, b_hh);
    head_kernel<<<Bb / 8, 256>>>(x, W1, b1, W2, b2, W3, b3, out);
    (void)in_sizes; (void)n_in; (void)out_size;
}